// round 7
// baseline (speedup 1.0000x reference)
#include <cuda_runtime.h>

typedef unsigned long long ull;

#define NTHR   256
#define TLEN   168
#define SEQ    169
#define NB     32
#define GRID   128
#define NSTEPS 24

__device__ float g_r1[(size_t)GRID * TLEN * 64 * 32];

static __device__ __forceinline__ void ffma2(ull& d, ull a, ull b) {
    asm("fma.rn.f32x2 %0, %1, %2, %0;" : "+l"(d) : "l"(a), "l"(b));
}
static __device__ __forceinline__ ull fadd2(ull a, ull b) {
    ull r; asm("add.rn.f32x2 %0, %1, %2;" : "=l"(r) : "l"(a), "l"(b)); return r;
}
static __device__ __forceinline__ ull splat(float w) {
    ull r; asm("mov.b64 %0, {%1, %1};" : "=l"(r) : "f"(w)); return r;
}
static __device__ __forceinline__ float2 unpk(ull v) {
    float2 r; asm("mov.b64 {%0, %1}, %2;" : "=f"(r.x), "=f"(r.y) : "l"(v)); return r;
}
static __device__ __forceinline__ ull pk(float a, float b) {
    ull r; asm("mov.b64 %0, {%1, %2};" : "=l"(r) : "f"(a), "f"(b)); return r;
}
static __device__ __forceinline__ float rcp_fast(float x) {
    float r; asm("rcp.approx.f32 %0, %1;" : "=f"(r) : "f"(x)); return r;
}
static __device__ __forceinline__ float sig_fast(float x) { return rcp_fast(1.0f + __expf(-x)); }
static __device__ __forceinline__ float tanh_fast(float x) { return fmaf(2.0f, sig_fast(2.0f * x), -1.0f); }

// Wt rows gate-interleaved: slot = unit*4 + gate. Thread keeps unit u=2rg+ks, batch octet bg.
template<int K2>
static __device__ __forceinline__ void matvec_fused(const float* __restrict__ Wt,
                                                    const float* __restrict__ hhr,
                                                    int rg, int bg, int ks,
                                                    ull gI[4], ull gF[4], ull gG[4], ull gO[4])
{
    ull acc[8][4];
    #pragma unroll
    for (int r = 0; r < 8; r++)
        #pragma unroll
        for (int c = 0; c < 4; c++) acc[r][c] = 0ull;
    const float4*     wp = (const float4*)Wt + rg * 2 + ks * (K2 * 64);
    const ulonglong2* hp = (const ulonglong2*)hhr + bg * 2 + ks * (K2 * 4);

    #pragma unroll 4
    for (int k = 0; k < K2; k++) {
        float4     wA = wp[k * 64];
        float4     wB = wp[k * 64 + 1];
        ulonglong2 hA = hp[k * 4];
        ulonglong2 hB = hp[k * 4 + 1];
        ull s0 = splat(wA.x), s1 = splat(wA.y), s2 = splat(wA.z), s3 = splat(wA.w);
        ull s4 = splat(wB.x), s5 = splat(wB.y), s6 = splat(wB.z), s7 = splat(wB.w);
        ffma2(acc[0][0], s0, hA.x); ffma2(acc[0][1], s0, hA.y); ffma2(acc[0][2], s0, hB.x); ffma2(acc[0][3], s0, hB.y);
        ffma2(acc[1][0], s1, hA.x); ffma2(acc[1][1], s1, hA.y); ffma2(acc[1][2], s1, hB.x); ffma2(acc[1][3], s1, hB.y);
        ffma2(acc[2][0], s2, hA.x); ffma2(acc[2][1], s2, hA.y); ffma2(acc[2][2], s2, hB.x); ffma2(acc[2][3], s2, hB.y);
        ffma2(acc[3][0], s3, hA.x); ffma2(acc[3][1], s3, hA.y); ffma2(acc[3][2], s3, hB.x); ffma2(acc[3][3], s3, hB.y);
        ffma2(acc[4][0], s4, hA.x); ffma2(acc[4][1], s4, hA.y); ffma2(acc[4][2], s4, hB.x); ffma2(acc[4][3], s4, hB.y);
        ffma2(acc[5][0], s5, hA.x); ffma2(acc[5][1], s5, hA.y); ffma2(acc[5][2], s5, hB.x); ffma2(acc[5][3], s5, hB.y);
        ffma2(acc[6][0], s6, hA.x); ffma2(acc[6][1], s6, hA.y); ffma2(acc[6][2], s6, hB.x); ffma2(acc[6][3], s6, hB.y);
        ffma2(acc[7][0], s7, hA.x); ffma2(acc[7][1], s7, hA.y); ffma2(acc[7][2], s7, hB.x); ffma2(acc[7][3], s7, hB.y);
    }
    #pragma unroll
    for (int r = 0; r < 8; r++)
        #pragma unroll
        for (int c = 0; c < 4; c++)
            acc[r][c] = fadd2(acc[r][c], __shfl_xor_sync(0xffffffffu, acc[r][c], 16));
    #pragma unroll
    for (int j = 0; j < 4; j++) {
        gI[j] = ks ? acc[4][j] : acc[0][j];
        gF[j] = ks ? acc[5][j] : acc[1][j];
        gG[j] = ks ? acc[6][j] : acc[2][j];
        gO[j] = ks ? acc[7][j] : acc[3][j];
    }
}

static __device__ __forceinline__ void act_core(const ull gI[4], const ull gF[4],
                                                const ull gG[4], const ull gO[4],
                                                ull c[4], ull hp_[4], ull rp_[4])
{
    #pragma unroll
    for (int j = 0; j < 4; j++) {
        float2 I = unpk(gI[j]), F = unpk(gF[j]), G = unpk(gG[j]), O = unpk(gO[j]), C = unpk(c[j]);
        float c0 = fmaf(sig_fast(F.x), C.x, sig_fast(I.x) * tanh_fast(G.x));
        float c1 = fmaf(sig_fast(F.y), C.y, sig_fast(I.y) * tanh_fast(G.y));
        c[j] = pk(c0, c1);
        float h0 = sig_fast(O.x) * tanh_fast(c0);
        float h1 = sig_fast(O.y) * tanh_fast(c1);
        hp_[j] = pk(h0, h1);
        rp_[j] = pk(fmaxf(h0, 0.0f), fmaxf(h1, 0.0f));
    }
}

__global__ void __launch_bounds__(NTHR, 1)
lstm_rec_kernel(const float* __restrict__ x,
                const float* __restrict__ Wih1, const float* __restrict__ Whh1,
                const float* __restrict__ bih1, const float* __restrict__ bhh1,
                const float* __restrict__ Wih2, const float* __restrict__ Whh2,
                const float* __restrict__ bih2, const float* __restrict__ bhh2,
                const float* __restrict__ fc1w, const float* __restrict__ fc1b,
                const float* __restrict__ fc2w, const float* __restrict__ fc2b,
                float* __restrict__ out)
{
    extern __shared__ float sm[];
    float* Wt    = sm;            // [128][256] gate-interleaved   32768
    float* hh    = Wt + 32768;    // 2 x [128][16]                  4096
    float* win   = hh + 4096;     // [192][32] t-major              6144
    float* wcomb = win + 6144;    // 65
    float* bcs   = wcomb + 65;    // 1
    float* dsh   = bcs + 1;       // 32

    const int tid   = threadIdx.x;
    const int b0    = blockIdx.x * NB;
    const int group = tid >> 7;
    const int gtid  = tid & 127;
    const int warp  = gtid >> 5;
    const int lane  = gtid & 31;
    const int ks    = lane >> 4;
    const int bg    = lane & 1;
    const int rg    = (warp << 3) | ((lane >> 1) & 7);
    const int u     = 2 * rg + ks;

    float* hhg = hh + group * 2048;
    const size_t r1_base = (size_t)blockIdx.x * TLEN * 2048 + (size_t)(group * 16 + bg * 8);
    #define R1_PTR(t_) (g_r1 + r1_base + ((size_t)(t_) * 64 + u) * 32)

    for (int i = tid; i < TLEN * 32; i += NTHR) {
        int t = i >> 5, b = i & 31;
        win[t * 32 + b] = x[(size_t)(b0 + b) * SEQ + t];
    }
    if (tid < NB) dsh[tid] = x[(size_t)(b0 + tid) * SEQ + TLEN];
    if (tid < 65) {
        float s = 0.0f;
        for (int j = 0; j < 64; j++) s = fmaf(fc2w[j], fc1w[j * 65 + tid], s);
        wcomb[tid] = s;
    }
    if (tid == 65) {
        float s = fc2b[0];
        for (int j = 0; j < 64; j++) s = fmaf(fc2w[j], fc1b[j], s);
        *bcs = s;
    }
    ull wi1p[4], b1p[4], b2p[4];
    #pragma unroll
    for (int g = 0; g < 4; g++) {
        wi1p[g] = splat(Wih1[g * 64 + u]);
        b1p[g]  = splat(bih1[g * 64 + u] + bhh1[g * 64 + u]);
        b2p[g]  = splat(bih2[g * 64 + u] + bhh2[g * 64 + u]);
    }

    ull cst[4], r1n[4], gI[4], gF[4], gG[4], gO[4], hpr[4], rpr[4];

    for (int step = 0; step < NSTEPS; step++) {
        {   // stage W1 gate-interleaved
            int s = (tid & 63) * 4 + (tid >> 6);
            const float4* src = (const float4*)(Whh1 + tid * 64);
            #pragma unroll
            for (int q = 0; q < 16; q++) {
                float4 v = src[q];
                Wt[(4*q  ) * 256 + s] = v.x;
                Wt[(4*q+1) * 256 + s] = v.y;
                Wt[(4*q+2) * 256 + s] = v.z;
                Wt[(4*q+3) * 256 + s] = v.w;
            }
        }
        {
            ulonglong2 z = make_ulonglong2(0ull, 0ull);
            ((ulonglong2*)(hhg + u * 16))[bg * 2]     = z;
            ((ulonglong2*)(hhg + u * 16))[bg * 2 + 1] = z;
        }
        #pragma unroll
        for (int j = 0; j < 4; j++) cst[j] = 0ull;
        __syncthreads();

        // ===== layer 1: anti-phase matvec/act =====
        for (int p = 0; p < 2 * TLEN + 1; p++) {
            if (((p ^ group) & 1) == 0) {
                int t = (p - group) >> 1;
                if (t < TLEN)
                    matvec_fused<32>(Wt, hhg, rg, bg, ks, gI, gF, gG, gO);
            } else {
                int t = (p - 1 - group) >> 1;
                if (t >= 0) {
                    const ulonglong2* xw = (const ulonglong2*)(win + (step + t) * 32 + group * 16) + bg * 2;
                    ulonglong2 xa = xw[0], xb = xw[1];
                    ull xt[4] = {xa.x, xa.y, xb.x, xb.y};
                    #pragma unroll
                    for (int j = 0; j < 4; j++) {
                        ull tI = b1p[0]; ffma2(tI, xt[j], wi1p[0]); gI[j] = fadd2(gI[j], tI);
                        ull tF = b1p[1]; ffma2(tF, xt[j], wi1p[1]); gF[j] = fadd2(gF[j], tF);
                        ull tG = b1p[2]; ffma2(tG, xt[j], wi1p[2]); gG[j] = fadd2(gG[j], tG);
                        ull tO = b1p[3]; ffma2(tO, xt[j], wi1p[3]); gO[j] = fadd2(gO[j], tO);
                    }
                    act_core(gI, gF, gG, gO, cst, hpr, rpr);
                    ((ulonglong2*)(hhg + u * 16))[bg * 2]     = make_ulonglong2(hpr[0], hpr[1]);
                    ((ulonglong2*)(hhg + u * 16))[bg * 2 + 1] = make_ulonglong2(hpr[2], hpr[3]);
                    float* rp = R1_PTR(t);
                    ((ulonglong2*)rp)[0] = make_ulonglong2(rpr[0], rpr[1]);
                    ((ulonglong2*)rp)[1] = make_ulonglong2(rpr[2], rpr[3]);
                }
            }
            __syncthreads();
        }

        // ---- transition + stage W2 ----
        {
            int s = (tid & 63) * 4 + (tid >> 6);
            const float4* s1 = (const float4*)(Wih2 + tid * 64);
            const float4* s2 = (const float4*)(Whh2 + tid * 64);
            #pragma unroll
            for (int q = 0; q < 16; q++) {
                float4 v = s1[q];
                Wt[(4*q  ) * 256 + s] = v.x;
                Wt[(4*q+1) * 256 + s] = v.y;
                Wt[(4*q+2) * 256 + s] = v.z;
                Wt[(4*q+3) * 256 + s] = v.w;
                float4 w = s2[q];
                Wt[(64+4*q  ) * 256 + s] = w.x;
                Wt[(64+4*q+1) * 256 + s] = w.y;
                Wt[(64+4*q+2) * 256 + s] = w.z;
                Wt[(64+4*q+3) * 256 + s] = w.w;
            }
        }
        {
            ((ulonglong2*)(hhg + (64 + u) * 16))[bg * 2]     = make_ulonglong2(hpr[0], hpr[1]);  // h2_0 = h1_T
            ((ulonglong2*)(hhg + (64 + u) * 16))[bg * 2 + 1] = make_ulonglong2(hpr[2], hpr[3]);
            const ulonglong2* r0 = (const ulonglong2*)R1_PTR(0);
            ulonglong2 a = r0[0], b = r0[1];
            ((ulonglong2*)(hhg + u * 16))[bg * 2]     = a;
            ((ulonglong2*)(hhg + u * 16))[bg * 2 + 1] = b;
            const ulonglong2* r1 = (const ulonglong2*)R1_PTR(1);
            ulonglong2 c2 = r1[0], d2 = r1[1];
            r1n[0] = c2.x; r1n[1] = c2.y; r1n[2] = d2.x; r1n[3] = d2.y;
        }
        __syncthreads();

        // ===== layer 2: anti-phase matvec/act =====
        for (int p = 0; p < 2 * TLEN + 1; p++) {
            if (((p ^ group) & 1) == 0) {
                int t = (p - group) >> 1;
                if (t < TLEN)
                    matvec_fused<64>(Wt, hhg, rg, bg, ks, gI, gF, gG, gO);
            } else {
                int t = (p - 1 - group) >> 1;
                if (t >= 0) {
                    #pragma unroll
                    for (int j = 0; j < 4; j++) {
                        gI[j] = fadd2(gI[j], b2p[0]);
                        gF[j] = fadd2(gF[j], b2p[1]);
                        gG[j] = fadd2(gG[j], b2p[2]);
                        gO[j] = fadd2(gO[j], b2p[3]);
                    }
                    act_core(gI, gF, gG, gO, cst, hpr, rpr);
                    ((ulonglong2*)(hhg + (64 + u) * 16))[bg * 2]     = make_ulonglong2(hpr[0], hpr[1]);
                    ((ulonglong2*)(hhg + (64 + u) * 16))[bg * 2 + 1] = make_ulonglong2(hpr[2], hpr[3]);
                    ((ulonglong2*)(hhg + u * 16))[bg * 2]     = make_ulonglong2(r1n[0], r1n[1]);
                    ((ulonglong2*)(hhg + u * 16))[bg * 2 + 1] = make_ulonglong2(r1n[2], r1n[3]);
                    if (t + 2 < TLEN) {
                        const ulonglong2* rn = (const ulonglong2*)R1_PTR(t + 2);
                        ulonglong2 a = rn[0], b = rn[1];
                        r1n[0] = a.x; r1n[1] = a.y; r1n[2] = b.x; r1n[3] = b.y;
                    }
                }
            }
            __syncthreads();
        }

        // ===== FC (collapsed) + window append =====
        if (tid < NB) {
            const float* h2 = hh + (tid >> 4) * 2048 + (tid & 15);
            float s = *bcs + wcomb[64] * dsh[tid];
            #pragma unroll
            for (int uu = 0; uu < 64; uu++)
                s = fmaf(wcomb[uu], fmaxf(h2[(64 + uu) * 16], 0.0f), s);
            out[(size_t)(b0 + tid) * NSTEPS + step] = s;
            win[(TLEN + step) * 32 + tid] = s;
        }
        __syncthreads();
    }
    #undef R1_PTR
}

extern "C" void kernel_launch(void* const* d_in, const int* in_sizes, int n_in,
                              void* d_out, int out_size) {
    (void)in_sizes; (void)n_in; (void)out_size;
    const float* x    = (const float*)d_in[0];
    const float* Wih1 = (const float*)d_in[1];
    const float* Whh1 = (const float*)d_in[2];
    const float* bih1 = (const float*)d_in[3];
    const float* bhh1 = (const float*)d_in[4];
    const float* Wih2 = (const float*)d_in[5];
    const float* Whh2 = (const float*)d_in[6];
    const float* bih2 = (const float*)d_in[7];
    const float* bhh2 = (const float*)d_in[8];
    const float* fc1w = (const float*)d_in[9];
    const float* fc1b = (const float*)d_in[10];
    const float* fc2w = (const float*)d_in[11];
    const float* fc2b = (const float*)d_in[12];
    float* out = (float*)d_out;

    size_t smem = (size_t)(32768 + 4096 + 6144 + 65 + 1 + NB) * sizeof(float);
    cudaFuncSetAttribute(lstm_rec_kernel, cudaFuncAttributeMaxDynamicSharedMemorySize, (int)smem);
    lstm_rec_kernel<<<GRID, NTHR, smem>>>(x, Wih1, Whh1, bih1, bhh1,
                                          Wih2, Whh2, bih2, bhh2,
                                          fc1w, fc1b, fc2w, fc2b, out);
}